// round 1
// baseline (speedup 1.0000x reference)
#include <cuda_runtime.h>
#include <cstdint>

#define NB 2
#define NT 2048
#define NV 32000
#define NE 512
#define NH 1024
#define NM 128
#define NROW (NB*NT)      // 4096
#define GRU_CTAS 128

// ---------------- scratch (module-static device memory; no cudaMalloc) -------
__device__ __align__(16) float g_emb[NROW*NE];                 // 8 MB
__device__ __align__(16) float g_xproj[(size_t)NROW*3*NH];     // 48 MB
__device__ __align__(16) float g_states[(size_t)NROW*NH];      // 16 MB
__device__ __align__(16) float g_head[(size_t)NROW*4*NE];      // 32 MB
__device__ __align__(16) float g_bfeat[NROW*NE];               // 8 MB
__device__ __align__(16) float g_q[NROW*NM];
__device__ __align__(16) float g_k[NROW*NM];
__device__ __align__(16) float g_gate[NROW];
__device__ __align__(16) float g_h[2][NB*NH];                  // double-buffered GRU state
__device__ int g_cnt[NT];                                      // per-step barrier counters

// ---------------- 1) embedding gather + smear (also zero counters/h0) --------
__global__ void __launch_bounds__(256) embed_kernel(
    const int* __restrict__ ids, const float* __restrict__ table,
    const float* __restrict__ smear_w, const float* __restrict__ smear_lambda)
{
    const int bt  = blockIdx.x;
    const int tid = threadIdx.x;
    if (tid == 0 && bt < NT)    g_cnt[bt] = 0;
    if (tid == 1 && bt < NB*NH) g_h[0][bt] = 0.f;

    const int t  = bt % NT;
    const int id = ids[bt];
    __shared__ float sgate;

    float v = 0.f;
    if (tid < 24) v = table[(size_t)id*NE + tid] * smear_w[tid];
    if (tid < 32) {
        #pragma unroll
        for (int off = 16; off; off >>= 1) v += __shfl_xor_sync(0xffffffffu, v, off);
        if (tid == 0) {
            float lam = smear_lambda[0];
            sgate = (t > 0) ? lam * (1.f/(1.f + __expf(-v))) : 0.f;
        }
    }
    __syncthreads();
    const float gate = sgate;
    const int idp = (t > 0) ? ids[bt-1] : 0;
    const float* rc = table + (size_t)id *NE;
    const float* rp = table + (size_t)idp*NE;
    for (int e = tid; e < NE; e += 256)
        g_emb[(size_t)bt*NE + e] = rc[e] + gate*rp[e];
}

// ---------------- generic fp32 NT GEMM: C[M,N] = A[M,K] * B[N,K]^T + bias ----
// BM=BN=128, BK=8, 256 threads, 8x8 per thread, double-buffered SMEM.
// act: 0 = none, 1 = relu^2
__global__ void __launch_bounds__(256) sgemm_nt(
    const float* __restrict__ A, const float* __restrict__ B,
    const float* __restrict__ bias, float* __restrict__ C,
    int M, int N, int K, int act)
{
    __shared__ __align__(16) float As[2][8][128];
    __shared__ __align__(16) float Bs[2][8][128];

    const int tid = threadIdx.x;
    const int bm = blockIdx.y << 7;
    const int bn = blockIdx.x << 7;
    const int lrow = tid >> 1;
    const int lcol = (tid & 1) << 2;

    const float* Ap = A + (size_t)(bm + lrow)*K + lcol;
    const float* Bp = B + (size_t)(bn + lrow)*K + lcol;

    float4 a4 = *(const float4*)Ap;
    float4 b4 = *(const float4*)Bp;
    As[0][lcol+0][lrow]=a4.x; As[0][lcol+1][lrow]=a4.y;
    As[0][lcol+2][lrow]=a4.z; As[0][lcol+3][lrow]=a4.w;
    Bs[0][lcol+0][lrow]=b4.x; Bs[0][lcol+1][lrow]=b4.y;
    Bs[0][lcol+2][lrow]=b4.z; Bs[0][lcol+3][lrow]=b4.w;
    __syncthreads();

    const int n0 = (tid & 15) << 3;
    const int m0 = (tid >> 4) << 3;

    float acc[8][8];
    #pragma unroll
    for (int i = 0; i < 8; i++)
        #pragma unroll
        for (int j = 0; j < 8; j++) acc[i][j] = 0.f;

    const int nk = K >> 3;
    for (int kt = 0; kt < nk; kt++) {
        const int buf = kt & 1;
        float4 na, nb;
        if (kt + 1 < nk) {
            na = *(const float4*)(Ap + (kt+1)*8);
            nb = *(const float4*)(Bp + (kt+1)*8);
        }
        #pragma unroll
        for (int k = 0; k < 8; k++) {
            float4 x0 = *(const float4*)&As[buf][k][m0];
            float4 x1 = *(const float4*)&As[buf][k][m0+4];
            float4 y0 = *(const float4*)&Bs[buf][k][n0];
            float4 y1 = *(const float4*)&Bs[buf][k][n0+4];
            float ar[8] = {x0.x,x0.y,x0.z,x0.w,x1.x,x1.y,x1.z,x1.w};
            float br[8] = {y0.x,y0.y,y0.z,y0.w,y1.x,y1.y,y1.z,y1.w};
            #pragma unroll
            for (int i = 0; i < 8; i++)
                #pragma unroll
                for (int j = 0; j < 8; j++)
                    acc[i][j] += ar[i]*br[j];
        }
        if (kt + 1 < nk) {
            const int nbuf = buf ^ 1;
            As[nbuf][lcol+0][lrow]=na.x; As[nbuf][lcol+1][lrow]=na.y;
            As[nbuf][lcol+2][lrow]=na.z; As[nbuf][lcol+3][lrow]=na.w;
            Bs[nbuf][lcol+0][lrow]=nb.x; Bs[nbuf][lcol+1][lrow]=nb.y;
            Bs[nbuf][lcol+2][lrow]=nb.z; Bs[nbuf][lcol+3][lrow]=nb.w;
            __syncthreads();
        }
    }

    float bv[8];
    #pragma unroll
    for (int j = 0; j < 8; j++) bv[j] = bias[bn + n0 + j];
    #pragma unroll
    for (int i = 0; i < 8; i++) {
        float* crow = C + (size_t)(bm + m0 + i)*N + bn + n0;
        float o[8];
        #pragma unroll
        for (int j = 0; j < 8; j++) {
            float v = acc[i][j] + bv[j];
            if (act == 1) { v = fmaxf(v, 0.f); v = v*v; }
            o[j] = v;
        }
        *(float4*)(crow)   = make_float4(o[0],o[1],o[2],o[3]);
        *(float4*)(crow+4) = make_float4(o[4],o[5],o[6],o[7]);
    }
}

// ---------------- 3) persistent GRU scan ------------------------------------
// 128 CTAs, each owns h-indices [cta*8, cta*8+8) and the 24 matching w_hh rows
// (3 gates x 8) resident in SMEM (96 KB). Per step: grid barrier via g_cnt,
// stage full h (2 batches x 1024) from L2 (L1 bypassed), 48 fp32 dots, gates.
__global__ void __launch_bounds__(256) gru_kernel(
    const float* __restrict__ w_hh, const float* __restrict__ b_hh)
{
    extern __shared__ float smem[];
    float* sw  = smem;             // 24*1024 weights
    float* sh  = sw + 24*NH;       // 2048 h (batch0 then batch1)
    float* sgh = sh + 2*NH;        // 48: [row(0..23)][batch]
    float* sx  = sgh + 48;         // 48: gate*16 + b*8 + j'

    const int tid = threadIdx.x;
    const int j0  = blockIdx.x << 3;

    #pragma unroll
    for (int r = 0; r < 24; r++) {
        const int gate = r >> 3, jp = r & 7;
        const float4* src = (const float4*)(w_hh + (size_t)(gate*NH + j0 + jp)*NH);
        ((float4*)(sw + r*NH))[tid] = src[tid];   // 256 float4 per row
    }
    float bh_r = 0.f, bh_z = 0.f, bh_n = 0.f;
    const int jp_g = tid & 7, b_g = (tid >> 3) & 1;
    if (tid < 16) {
        bh_r = b_hh[        j0 + jp_g];
        bh_z = b_hh[  NH  + j0 + jp_g];
        bh_n = b_hh[2*NH  + j0 + jp_g];
    }
    __syncthreads();

    const int warp = tid >> 5, lane = tid & 31;
    const int r0 = warp*3;
    const float4* sw4 = (const float4*)sw;
    const float4* sh4 = (const float4*)sh;

    for (int t = 0; t < NT; t++) {
        // prefetch this CTA's x_proj slice (issued before the barrier wait)
        float xval = 0.f;
        if (tid < 48) {
            const int gate = tid >> 4;
            const int bb   = (tid >> 3) & 1;
            const int jp   = tid & 7;
            xval = g_xproj[((size_t)(bb*NT + t))*(3*NH) + gate*NH + j0 + jp];
        }
        if (t > 0) {
            if (tid == 0) { while (((volatile int*)g_cnt)[t-1] < GRU_CTAS) { } }
            __syncthreads();
        }
        {   // stage h (bypass L1: buffer addresses are reused every 2 steps)
            const float4* hsrc = (const float4*)g_h[t & 1];
            float4 hv0 = __ldcg(hsrc + tid);
            float4 hv1 = __ldcg(hsrc + 256 + tid);
            ((float4*)sh)[tid]       = hv0;
            ((float4*)sh)[256 + tid] = hv1;
        }
        if (tid < 48) sx[tid] = xval;
        __syncthreads();

        float a00=0,a01=0,a10=0,a11=0,a20=0,a21=0;
        #pragma unroll
        for (int i = 0; i < 8; i++) {
            const int idx = (i << 5) + lane;
            float4 h0 = sh4[idx];
            float4 h1 = sh4[256 + idx];
            float4 w0 = sw4[(r0+0)*256 + idx];
            float4 w1 = sw4[(r0+1)*256 + idx];
            float4 w2 = sw4[(r0+2)*256 + idx];
            a00 += w0.x*h0.x + w0.y*h0.y + w0.z*h0.z + w0.w*h0.w;
            a01 += w0.x*h1.x + w0.y*h1.y + w0.z*h1.z + w0.w*h1.w;
            a10 += w1.x*h0.x + w1.y*h0.y + w1.z*h0.z + w1.w*h0.w;
            a11 += w1.x*h1.x + w1.y*h1.y + w1.z*h1.z + w1.w*h1.w;
            a20 += w2.x*h0.x + w2.y*h0.y + w2.z*h0.z + w2.w*h0.w;
            a21 += w2.x*h1.x + w2.y*h1.y + w2.z*h1.z + w2.w*h1.w;
        }
        #pragma unroll
        for (int off = 16; off; off >>= 1) {
            a00 += __shfl_down_sync(0xffffffffu, a00, off);
            a01 += __shfl_down_sync(0xffffffffu, a01, off);
            a10 += __shfl_down_sync(0xffffffffu, a10, off);
            a11 += __shfl_down_sync(0xffffffffu, a11, off);
            a20 += __shfl_down_sync(0xffffffffu, a20, off);
            a21 += __shfl_down_sync(0xffffffffu, a21, off);
        }
        if (lane == 0) {
            sgh[(r0+0)*2+0]=a00; sgh[(r0+0)*2+1]=a01;
            sgh[(r0+1)*2+0]=a10; sgh[(r0+1)*2+1]=a11;
            sgh[(r0+2)*2+0]=a20; sgh[(r0+2)*2+1]=a21;
        }
        __syncthreads();
        if (tid < 16) {
            const int jp = jp_g, bb = b_g;
            float hr = sgh[( 0 + jp)*2 + bb] + bh_r;
            float hz = sgh[( 8 + jp)*2 + bb] + bh_z;
            float hn = sgh[(16 + jp)*2 + bb] + bh_n;
            float xr = sx[      bb*8 + jp];
            float xz = sx[16 +  bb*8 + jp];
            float xn = sx[32 +  bb*8 + jp];
            float rr = 1.f/(1.f + __expf(-(xr + hr)));
            float zz = 1.f/(1.f + __expf(-(xz + hz)));
            float nn = tanhf(xn + rr*hn);
            float hold = sh[bb*NH + j0 + jp];
            float hnew = (1.f - zz)*nn + zz*hold;
            g_states[((size_t)(bb*NT + t))*NH + j0 + jp] = hnew;
            __stcg(&g_h[(t+1)&1][bb*NH + j0 + jp], hnew);
        }
        __threadfence();
        __syncthreads();
        if (tid == 0) atomicAdd(&g_cnt[t], 1);
    }
}

// ---------------- 7) g = sigmoid(states @ wg^T + bg) ------------------------
__global__ void __launch_bounds__(256) g_kernel(
    const float* __restrict__ wg, const float* __restrict__ bg)
{
    const int row  = (blockIdx.x << 3) + (threadIdx.x >> 5);
    const int lane = threadIdx.x & 31;
    const float* s = g_states + (size_t)row*NH;
    float acc = 0.f;
    #pragma unroll 8
    for (int i = 0; i < 32; i++) acc += s[lane + (i<<5)] * wg[lane + (i<<5)];
    #pragma unroll
    for (int off = 16; off; off >>= 1) acc += __shfl_xor_sync(0xffffffffu, acc, off);
    if (lane == 0) g_gate[row] = 1.f/(1.f + __expf(-(acc + bg[0])));
}

// ---------------- 8) strictly-causal attention + fused vocab scatter --------
__global__ void __launch_bounds__(256) attn_kernel(
    const int* __restrict__ ids, float* __restrict__ out,
    const float* __restrict__ mscale_p)
{
    const int t = blockIdx.x;
    const int b = blockIdx.y;
    if (t == 0) return;   // row 0 contributes nothing (empty strict-causal set)

    __shared__ float sc[NT];
    __shared__ __align__(16) float qs[NM];
    __shared__ float red[8];
    const int tid = threadIdx.x;
    const int lane = tid & 31, wp = tid >> 5;

    if (tid < NM) qs[tid] = g_q[((size_t)(b*NT + t))*NM + tid];
    __syncthreads();
    const float4* q4 = (const float4*)qs;

    float lmax = -1e30f;
    for (int s = tid; s < t; s += 256) {
        const float4* k4 = (const float4*)(g_k + ((size_t)(b*NT + s))*NM);
        float acc = 0.f;
        #pragma unroll
        for (int c = 0; c < 32; c++) {
            float4 qv = q4[c]; float4 kv = k4[c];
            acc += qv.x*kv.x + qv.y*kv.y + qv.z*kv.z + qv.w*kv.w;
        }
        acc *= 0.0883883476483184f;  // 1/sqrt(128)
        sc[s] = acc;
        lmax = fmaxf(lmax, acc);
    }
    #pragma unroll
    for (int off = 16; off; off >>= 1) lmax = fmaxf(lmax, __shfl_xor_sync(0xffffffffu, lmax, off));
    if (lane == 0) red[wp] = lmax;
    __syncthreads();
    if (tid == 0) {
        float m = red[0];
        #pragma unroll
        for (int i = 1; i < 8; i++) m = fmaxf(m, red[i]);
        red[0] = m;
    }
    __syncthreads();
    const float smax = red[0];
    __syncthreads();

    float lsum = 0.f;
    for (int s = tid; s < t; s += 256) {
        float e = __expf(sc[s] - smax);
        sc[s] = e;
        lsum += e;
    }
    #pragma unroll
    for (int off = 16; off; off >>= 1) lsum += __shfl_xor_sync(0xffffffffu, lsum, off);
    if (lane == 0) red[wp] = lsum;
    __syncthreads();
    if (tid == 0) {
        float ssum = 0.f;
        #pragma unroll
        for (int i = 0; i < 8; i++) ssum += red[i];
        red[0] = ssum;
    }
    __syncthreads();
    const float ssum = fmaxf(red[0], 1e-6f);
    const float scale = g_gate[b*NT + t] * mscale_p[0] / ssum;

    float* orow = out + ((size_t)(b*NT + t))*NV;
    const int* idr = ids + b*NT;
    for (int s = tid; s < t; s += 256)
        atomicAdd(&orow[idr[s]], sc[s]*scale);
}

// ---------------- launcher ---------------------------------------------------
extern "C" void kernel_launch(void* const* d_in, const int* in_sizes, int n_in,
                              void* d_out, int out_size)
{
    const int*   ids     = (const int*)  d_in[0];
    const float* table   = (const float*)d_in[1];
    const float* w_ih    = (const float*)d_in[2];
    const float* w_hh    = (const float*)d_in[3];
    const float* b_ih    = (const float*)d_in[4];
    const float* b_hh    = (const float*)d_in[5];
    const float* wq      = (const float*)d_in[6];
    const float* bq      = (const float*)d_in[7];
    const float* wk      = (const float*)d_in[8];
    const float* bk      = (const float*)d_in[9];
    const float* wg      = (const float*)d_in[10];
    const float* bg      = (const float*)d_in[11];
    const float* w_fc    = (const float*)d_in[12];
    const float* b_fc    = (const float*)d_in[13];
    const float* w_proj  = (const float*)d_in[14];
    const float* b_proj  = (const float*)d_in[15];
    const float* out_b   = (const float*)d_in[16];
    const float* mscale  = (const float*)d_in[17];
    const float* smear_w = (const float*)d_in[18];
    const float* smear_l = (const float*)d_in[19];
    float* out = (float*)d_out;
    (void)in_sizes; (void)n_in; (void)out_size;

    void *p_emb, *p_xproj, *p_states, *p_head, *p_bfeat, *p_q, *p_k;
    cudaGetSymbolAddress(&p_emb,    g_emb);
    cudaGetSymbolAddress(&p_xproj,  g_xproj);
    cudaGetSymbolAddress(&p_states, g_states);
    cudaGetSymbolAddress(&p_head,   g_head);
    cudaGetSymbolAddress(&p_bfeat,  g_bfeat);
    cudaGetSymbolAddress(&p_q,      g_q);
    cudaGetSymbolAddress(&p_k,      g_k);

    const int gru_smem = (24*NH + 2*NH + 48 + 48) * (int)sizeof(float); // 106,880 B
    cudaFuncSetAttribute(gru_kernel, cudaFuncAttributeMaxDynamicSharedMemorySize, gru_smem);

    // 1) embedding + smear (+ zero barrier counters and h0)
    embed_kernel<<<NROW, 256>>>(ids, table, smear_w, smear_l);
    // 2) x_proj = emb @ w_ih^T + b_ih            [4096,3072]
    sgemm_nt<<<dim3(24,32), 256>>>((const float*)p_emb, w_ih, b_ih,
                                   (float*)p_xproj, NROW, 3*NH, NE, 0);
    // 3) GRU scan -> states                      [4096,1024]
    gru_kernel<<<GRU_CTAS, 256, gru_smem>>>(w_hh, b_hh);
    // 4) head = relu^2(states @ w_fc^T + b_fc)   [4096,2048]
    sgemm_nt<<<dim3(16,32), 256>>>((const float*)p_states, w_fc, b_fc,
                                   (float*)p_head, NROW, 4*NE, NH, 1);
    // 5) base_feat = head @ w_proj^T + b_proj    [4096,512]
    sgemm_nt<<<dim3(4,32), 256>>>((const float*)p_head, w_proj, b_proj,
                                  (float*)p_bfeat, NROW, NE, 4*NE, 0);
    // 6) logits = base_feat @ emb_table^T + output_bias -> d_out [4096,32000]
    sgemm_nt<<<dim3(250,32), 256>>>((const float*)p_bfeat, table, out_b,
                                    out, NROW, NV, NE, 0);
    // 7) q, k                                     [4096,128] each
    sgemm_nt<<<dim3(1,32), 256>>>((const float*)p_states, wq, bq,
                                  (float*)p_q, NROW, NM, NH, 0);
    sgemm_nt<<<dim3(1,32), 256>>>((const float*)p_states, wk, bk,
                                  (float*)p_k, NROW, NM, NH, 0);
    // 8) g = sigmoid(states @ wg^T + bg)
    g_kernel<<<NROW/8, 256>>>(wg, bg);
    // 9) causal attention + scatter-add into d_out
    attn_kernel<<<dim3(NT, NB), 256>>>(ids, out, mscale);
}

// round 3
// speedup vs baseline: 1.2840x; 1.2840x over previous
#include <cuda_runtime.h>
#include <cuda_bf16.h>
#include <cstdint>

#define NB 2
#define NT 2048
#define NV 32000
#define NE 512
#define NH 1024
#define NM 128
#define NROW (NB*NT)      // 4096
#define GRU_CTAS 128

// ---------------- scratch (module-static device memory; no cudaMalloc) -------
__device__ __align__(16) float g_emb[NROW*NE];
__device__ __align__(16) float g_xproj[(size_t)NROW*3*NH];
__device__ __align__(16) float g_states[(size_t)NROW*NH];
__device__ __align__(16) float g_head[(size_t)NROW*4*NE];
__device__ __align__(16) float g_bfeat[NROW*NE];
__device__ __align__(16) float g_q[NROW*NM];
__device__ __align__(16) float g_k[NROW*NM];
__device__ __align__(16) float g_gate[NROW];
__device__ __align__(16) float g_h[2][NB*NH];
__device__ int g_cnt[NT];

// bf16 triple-expanded operands (K' = 3K)
__device__ __align__(16) __nv_bfloat16 x_e3  [(size_t)NROW*3*NE];
__device__ __align__(16) __nv_bfloat16 x_wih3[(size_t)3*NH*3*NE];
__device__ __align__(16) __nv_bfloat16 x_s3  [(size_t)NROW*3*NH];
__device__ __align__(16) __nv_bfloat16 x_wfc3[(size_t)4*NE*3*NH];
__device__ __align__(16) __nv_bfloat16 x_hd3 [(size_t)NROW*3*4*NE];
__device__ __align__(16) __nv_bfloat16 x_wp3 [(size_t)NE*3*4*NE];
__device__ __align__(16) __nv_bfloat16 x_f3  [(size_t)NROW*3*NE];
__device__ __align__(16) __nv_bfloat16 x_t3  [(size_t)NV*3*NE];
__device__ __align__(16) __nv_bfloat16 x_wq3 [(size_t)NM*3*NH];
__device__ __align__(16) __nv_bfloat16 x_wk3 [(size_t)NM*3*NH];

// ---------------- operand expansion: fp32 -> triple bf16 ---------------------
// A-mode (per element): [hi, hi, lo] ; B-mode: [hi, lo, hi]
// products per k-triple: hi*hi + hi*lo + lo*hi  (fp32 accumulate)
__global__ void __launch_bounds__(256) expand3_kernel(
    const float* __restrict__ src, __nv_bfloat16* __restrict__ dst, int n8, int bmode)
{
    int i = blockIdx.x*256 + threadIdx.x;
    if (i >= n8) return;
    const float4* s4 = (const float4*)src + (size_t)i*2;
    float4 v0 = s4[0], v1 = s4[1];
    float a[8] = {v0.x, v0.y, v0.z, v0.w, v1.x, v1.y, v1.z, v1.w};
    __align__(16) __nv_bfloat16 o[24];
    #pragma unroll
    for (int j = 0; j < 8; j++) {
        float x = a[j];
        __nv_bfloat16 h = __float2bfloat16(x);
        __nv_bfloat16 l = __float2bfloat16(x - __bfloat162float(h));
        if (bmode) { o[3*j] = h; o[3*j+1] = l; o[3*j+2] = h; }
        else       { o[3*j] = h; o[3*j+1] = h; o[3*j+2] = l; }
    }
    uint4* d4 = (uint4*)(dst + (size_t)i*24);
    const uint4* ov = (const uint4*)o;
    d4[0] = ov[0]; d4[1] = ov[1]; d4[2] = ov[2];
}

// ================= HMMA (mma.sync) bf16 GEMM ================================
__device__ __forceinline__ uint32_t smem_u32(const void* p) {
    uint32_t a;
    asm("{ .reg .u64 t; cvta.to.shared.u64 t, %1; cvt.u32.u64 %0, t; }" : "=r"(a) : "l"(p));
    return a;
}

// swizzled byte offset inside a [128 rows][32 bf16] stage tile:
// 2 logical rows (64B each) per 128B physical row; 16B chunks XOR'ed by (p&7)
__device__ __forceinline__ int swoff(int row, int ch) {
    int p = row >> 1;
    return (p << 7) + (((((row & 1) << 2) | ch) ^ (p & 7)) << 4);
}

#define LDMX4(r0,r1,r2,r3, addr) \
    asm volatile("ldmatrix.sync.aligned.m8n8.x4.shared.b16 {%0,%1,%2,%3}, [%4];" \
        : "=r"(r0),"=r"(r1),"=r"(r2),"=r"(r3) : "r"(addr))

#define MMA16816(d, a, b0v, b1v) \
    asm volatile("mma.sync.aligned.m16n8k16.row.col.f32.bf16.bf16.f32 " \
        "{%0,%1,%2,%3}, {%4,%5,%6,%7}, {%8,%9}, {%0,%1,%2,%3};" \
        : "+f"((d)[0]),"+f"((d)[1]),"+f"((d)[2]),"+f"((d)[3]) \
        : "r"((a)[0]),"r"((a)[1]),"r"((a)[2]),"r"((a)[3]), "r"(b0v),"r"(b1v))

// C[M,N] = A3[M,K3] * B3[N,K3]^T + bias, act: 0 none, 1 relu^2
// BM=BN=128, BK=32 bf16, 256 threads (8 warps, 2m x 4n), double-buffered SMEM.
__global__ void __launch_bounds__(256) hmma_gemm(
    const __nv_bfloat16* __restrict__ A, const __nv_bfloat16* __restrict__ B,
    const float* __restrict__ bias, float* __restrict__ C,
    int M, int N, int K3, int act)
{
    __shared__ __align__(16) char smA[2][8192];
    __shared__ __align__(16) char smB[2][8192];

    const int tid  = threadIdx.x;
    const int lane = tid & 31, wid = tid >> 5;
    const int bm = blockIdx.y << 7, bn = blockIdx.x << 7;
    const int wm = (wid >> 2) << 6;   // 0 / 64
    const int wn = (wid & 3) << 5;    // 0 / 32 / 64 / 96

    // global<->smem staging map: 2 chunks of A + 2 of B per thread
    const int row0 = tid >> 2,        ch0 = tid & 3;          // cid = tid
    const int row1 = (tid + 256) >> 2, ch1 = tid & 3;         // cid = tid + 256
    const int so0 = swoff(row0, ch0), so1 = swoff(row1, ch1);
    const __nv_bfloat16* Ag0 = A + (size_t)(bm + row0)*K3 + ch0*8;
    const __nv_bfloat16* Ag1 = A + (size_t)(bm + row1)*K3 + ch1*8;
    const __nv_bfloat16* Bg0 = B + (size_t)(bn + row0)*K3 + ch0*8;
    const __nv_bfloat16* Bg1 = B + (size_t)(bn + row1)*K3 + ch1*8;

    // ldmatrix lane decode
    const int g = lane >> 3, rr = lane & 7;
    const int lrow_a = wm + ((g & 1) << 3) + rr;   // + mi*16
    const int lrow_b = wn + ((g & 1) << 3) + rr;   // + bi*16
    const int kc = g >> 1;                          // chunk within kstep
    const uint32_t baseA0 = smem_u32(smA[0]), baseA1 = smem_u32(smA[1]);
    const uint32_t baseB0 = smem_u32(smB[0]), baseB1 = smem_u32(smB[1]);

    float acc[4][4][4];
    #pragma unroll
    for (int i = 0; i < 4; i++)
        #pragma unroll
        for (int j = 0; j < 4; j++)
            #pragma unroll
            for (int r = 0; r < 4; r++) acc[i][j][r] = 0.f;

    // stage 0
    {
        uint4 a0 = *(const uint4*)Ag0, a1 = *(const uint4*)Ag1;
        uint4 b0 = *(const uint4*)Bg0, b1 = *(const uint4*)Bg1;
        *(uint4*)(smA[0] + so0) = a0; *(uint4*)(smA[0] + so1) = a1;
        *(uint4*)(smB[0] + so0) = b0; *(uint4*)(smB[0] + so1) = b1;
    }
    __syncthreads();

    const int nk = K3 >> 5;
    for (int kt = 0; kt < nk; kt++) {
        uint4 pa0, pa1, pb0, pb1;
        if (kt + 1 < nk) {
            const int ko = (kt + 1) << 5;
            pa0 = *(const uint4*)(Ag0 + ko); pa1 = *(const uint4*)(Ag1 + ko);
            pb0 = *(const uint4*)(Bg0 + ko); pb1 = *(const uint4*)(Bg1 + ko);
        }
        const uint32_t bA = (kt & 1) ? baseA1 : baseA0;
        const uint32_t bB = (kt & 1) ? baseB1 : baseB0;
        #pragma unroll
        for (int ks = 0; ks < 2; ks++) {
            const int chunk = (ks << 1) + kc;
            uint32_t af[4][4];
            #pragma unroll
            for (int mi = 0; mi < 4; mi++) {
                uint32_t ad = bA + swoff(lrow_a + (mi << 4), chunk);
                LDMX4(af[mi][0], af[mi][1], af[mi][2], af[mi][3], ad);
            }
            uint32_t bf[4][2];
            #pragma unroll
            for (int bi = 0; bi < 2; bi++) {
                uint32_t t0, t1, t2, t3;
                uint32_t ad = bB + swoff(lrow_b + (bi << 4), chunk);
                LDMX4(t0, t1, t2, t3, ad);
                bf[bi*2  ][0] = t0; bf[bi*2+1][0] = t1;
                bf[bi*2  ][1] = t2; bf[bi*2+1][1] = t3;
            }
            #pragma unroll
            for (int mi = 0; mi < 4; mi++)
                #pragma unroll
                for (int nj = 0; nj < 4; nj++)
                    MMA16816(acc[mi][nj], af[mi], bf[nj][0], bf[nj][1]);
        }
        if (kt + 1 < nk) {
            char* dA = (kt & 1) ? smA[0] : smA[1];
            char* dB = (kt & 1) ? smB[0] : smB[1];
            *(uint4*)(dA + so0) = pa0; *(uint4*)(dA + so1) = pa1;
            *(uint4*)(dB + so0) = pb0; *(uint4*)(dB + so1) = pb1;
            __syncthreads();
        }
    }

    // epilogue
    const int q  = lane >> 2;
    const int c2 = (lane & 3) << 1;
    #pragma unroll
    for (int mi = 0; mi < 4; mi++) {
        #pragma unroll
        for (int nj = 0; nj < 4; nj++) {
            const int col  = bn + wn + (nj << 3) + c2;
            const int row  = bm + wm + (mi << 4) + q;
            float b0v = bias[col], b1v = bias[col+1];
            float v0 = acc[mi][nj][0] + b0v;
            float v1 = acc[mi][nj][1] + b1v;
            float v2 = acc[mi][nj][2] + b0v;
            float v3 = acc[mi][nj][3] + b1v;
            if (act == 1) {
                v0 = fmaxf(v0, 0.f); v0 *= v0;
                v1 = fmaxf(v1, 0.f); v1 *= v1;
                v2 = fmaxf(v2, 0.f); v2 *= v2;
                v3 = fmaxf(v3, 0.f); v3 *= v3;
            }
            *(float2*)&C[(size_t)row*N + col]       = make_float2(v0, v1);
            *(float2*)&C[(size_t)(row + 8)*N + col] = make_float2(v2, v3);
        }
    }
}

// ---------------- 1) embedding gather + smear (also zero counters/h0) --------
__global__ void __launch_bounds__(256) embed_kernel(
    const int* __restrict__ ids, const float* __restrict__ table,
    const float* __restrict__ smear_w, const float* __restrict__ smear_lambda)
{
    const int bt  = blockIdx.x;
    const int tid = threadIdx.x;
    if (tid == 0 && bt < NT)    g_cnt[bt] = 0;
    if (tid == 1 && bt < NB*NH) g_h[0][bt] = 0.f;

    const int t  = bt % NT;
    const int id = ids[bt];
    __shared__ float sgate;

    float v = 0.f;
    if (tid < 24) v = table[(size_t)id*NE + tid] * smear_w[tid];
    if (tid < 32) {
        #pragma unroll
        for (int off = 16; off; off >>= 1) v += __shfl_xor_sync(0xffffffffu, v, off);
        if (tid == 0) {
            float lam = smear_lambda[0];
            sgate = (t > 0) ? lam * (1.f/(1.f + __expf(-v))) : 0.f;
        }
    }
    __syncthreads();
    const float gate = sgate;
    const int idp = (t > 0) ? ids[bt-1] : 0;
    const float* rc = table + (size_t)id *NE;
    const float* rp = table + (size_t)idp*NE;
    for (int e = tid; e < NE; e += 256)
        g_emb[(size_t)bt*NE + e] = rc[e] + gate*rp[e];
}

// ---------------- persistent GRU scan ----------------------------------------
__global__ void __launch_bounds__(256) gru_kernel(
    const float* __restrict__ w_hh, const float* __restrict__ b_hh)
{
    extern __shared__ float smem[];
    float* sw  = smem;             // 24*1024 weights
    float* sh  = sw + 24*NH;       // 2048 h
    float* sgh = sh + 2*NH;        // 48
    float* sx  = sgh + 48;         // 48

    const int tid = threadIdx.x;
    const int j0  = blockIdx.x << 3;

    #pragma unroll
    for (int r = 0; r < 24; r++) {
        const int gate = r >> 3, jp = r & 7;
        const float4* src = (const float4*)(w_hh + (size_t)(gate*NH + j0 + jp)*NH);
        ((float4*)(sw + r*NH))[tid] = src[tid];
    }
    float bh_r = 0.f, bh_z = 0.f, bh_n = 0.f;
    const int jp_g = tid & 7, b_g = (tid >> 3) & 1;
    if (tid < 16) {
        bh_r = b_hh[        j0 + jp_g];
        bh_z = b_hh[  NH  + j0 + jp_g];
        bh_n = b_hh[2*NH  + j0 + jp_g];
    }
    __syncthreads();

    const int warp = tid >> 5, lane = tid & 31;
    const int r0 = warp*3;
    const float4* sw4 = (const float4*)sw;
    const float4* sh4 = (const float4*)sh;

    for (int t = 0; t < NT; t++) {
        float xval = 0.f;
        if (tid < 48) {
            const int gate = tid >> 4;
            const int bb   = (tid >> 3) & 1;
            const int jp   = tid & 7;
            xval = g_xproj[((size_t)(bb*NT + t))*(3*NH) + gate*NH + j0 + jp];
        }
        if (t > 0) {
            if (tid == 0) { while (((volatile int*)g_cnt)[t-1] < GRU_CTAS) { } }
            __syncthreads();
        }
        {
            const float4* hsrc = (const float4*)g_h[t & 1];
            float4 hv0 = __ldcg(hsrc + tid);
            float4 hv1 = __ldcg(hsrc + 256 + tid);
            ((float4*)sh)[tid]       = hv0;
            ((float4*)sh)[256 + tid] = hv1;
        }
        if (tid < 48) sx[tid] = xval;
        __syncthreads();

        float a00=0,a01=0,a10=0,a11=0,a20=0,a21=0;
        #pragma unroll
        for (int i = 0; i < 8; i++) {
            const int idx = (i << 5) + lane;
            float4 h0 = sh4[idx];
            float4 h1 = sh4[256 + idx];
            float4 w0 = sw4[(r0+0)*256 + idx];
            float4 w1 = sw4[(r0+1)*256 + idx];
            float4 w2 = sw4[(r0+2)*256 + idx];
            a00 += w0.x*h0.x + w0.y*h0.y + w0.z*h0.z + w0.w*h0.w;
            a01 += w0.x*h1.x + w0.y*h1.y + w0.z*h1.z + w0.w*h1.w;
            a10 += w1.x*h0.x + w1.y*h0.y + w1.z*h0.z + w1.w*h0.w;
            a11 += w1.x*h1.x + w1.y*h1.y + w1.z*h1.z + w1.w*h1.w;
            a20 += w2.x*h0.x + w2.y*h0.y + w2.z*h0.z + w2.w*h0.w;
            a21 += w2.x*h1.x + w2.y*h1.y + w2.z*h1.z + w2.w*h1.w;
        }
        #pragma unroll
        for (int off = 16; off; off >>= 1) {
            a00 += __shfl_down_sync(0xffffffffu, a00, off);
            a01 += __shfl_down_sync(0xffffffffu, a01, off);
            a10 += __shfl_down_sync(0xffffffffu, a10, off);
            a11 += __shfl_down_sync(0xffffffffu, a11, off);
            a20 += __shfl_down_sync(0xffffffffu, a20, off);
            a21 += __shfl_down_sync(0xffffffffu, a21, off);
        }
        if (lane == 0) {
            sgh[(r0+0)*2+0]=a00; sgh[(r0+0)*2+1]=a01;
            sgh[(r0+1)*2+0]=a10; sgh[(r0+1)*2+1]=a11;
            sgh[(r0+2)*2+0]=a20; sgh[(r0+2)*2+1]=a21;
        }
        __syncthreads();
        if (tid < 16) {
            const int jp = jp_g, bb = b_g;
            float hr = sgh[( 0 + jp)*2 + bb] + bh_r;
            float hz = sgh[( 8 + jp)*2 + bb] + bh_z;
            float hn = sgh[(16 + jp)*2 + bb] + bh_n;
            float xr = sx[      bb*8 + jp];
            float xz = sx[16 +  bb*8 + jp];
            float xn = sx[32 +  bb*8 + jp];
            float rr = 1.f/(1.f + __expf(-(xr + hr)));
            float zz = 1.f/(1.f + __expf(-(xz + hz)));
            float nn = tanhf(xn + rr*hn);
            float hold = sh[bb*NH + j0 + jp];
            float hnew = (1.f - zz)*nn + zz*hold;
            g_states[((size_t)(bb*NT + t))*NH + j0 + jp] = hnew;
            __stcg(&g_h[(t+1)&1][bb*NH + j0 + jp], hnew);
        }
        __threadfence();
        __syncthreads();
        if (tid == 0) atomicAdd(&g_cnt[t], 1);
    }
}

// ---------------- g = sigmoid(states @ wg^T + bg) ----------------------------
__global__ void __launch_bounds__(256) g_kernel(
    const float* __restrict__ wg, const float* __restrict__ bg)
{
    const int row  = (blockIdx.x << 3) + (threadIdx.x >> 5);
    const int lane = threadIdx.x & 31;
    const float* s = g_states + (size_t)row*NH;
    float acc = 0.f;
    #pragma unroll 8
    for (int i = 0; i < 32; i++) acc += s[lane + (i<<5)] * wg[lane + (i<<5)];
    #pragma unroll
    for (int off = 16; off; off >>= 1) acc += __shfl_xor_sync(0xffffffffu, acc, off);
    if (lane == 0) g_gate[row] = 1.f/(1.f + __expf(-(acc + bg[0])));
}

// ---------------- causal attention + fused vocab scatter ---------------------
__global__ void __launch_bounds__(256) attn_kernel(
    const int* __restrict__ ids, float* __restrict__ out,
    const float* __restrict__ mscale_p)
{
    const int t = blockIdx.x;
    const int b = blockIdx.y;
    if (t == 0) return;

    __shared__ float sc[NT];
    __shared__ __align__(16) float qs[NM];
    __shared__ float red[8];
    const int tid = threadIdx.x;
    const int lane = tid & 31, wp = tid >> 5;

    if (tid < NM) qs[tid] = g_q[((size_t)(b*NT + t))*NM + tid];
    __syncthreads();
    const float4* q4 = (const float4*)qs;

    float lmax = -1e30f;
    for (int s = tid; s < t; s += 256) {
        const float4* k4 = (const float4*)(g_k + ((size_t)(b*NT + s))*NM);
        float acc = 0.f;
        #pragma unroll
        for (int c = 0; c < 32; c++) {
            float4 qv = q4[c]; float4 kv = k4[c];
            acc += qv.x*kv.x + qv.y*kv.y + qv.z*kv.z + qv.w*kv.w;
        }
        acc *= 0.0883883476483184f;
        sc[s] = acc;
        lmax = fmaxf(lmax, acc);
    }
    #pragma unroll
    for (int off = 16; off; off >>= 1) lmax = fmaxf(lmax, __shfl_xor_sync(0xffffffffu, lmax, off));
    if (lane == 0) red[wp] = lmax;
    __syncthreads();
    if (tid == 0) {
        float m = red[0];
        #pragma unroll
        for (int i = 1; i < 8; i++) m = fmaxf(m, red[i]);
        red[0] = m;
    }
    __syncthreads();
    const float smax = red[0];
    __syncthreads();

    float lsum = 0.f;
    for (int s = tid; s < t; s += 256) {
        float e = __expf(sc[s] - smax);
        sc[s] = e;
        lsum += e;
    }
    #pragma unroll
    for (int off = 16; off; off >>= 1) lsum += __shfl_xor_sync(0xffffffffu, lsum, off);
    if (lane == 0) red[wp] = lsum;
    __syncthreads();
    if (tid == 0) {
        float ssum = 0.f;
        #pragma unroll
        for (int i = 0; i < 8; i++) ssum += red[i];
        red[0] = ssum;
    }
    __syncthreads();
    const float ssum = fmaxf(red[0], 1e-6f);
    const float scale = g_gate[b*NT + t] * mscale_p[0] / ssum;

    float* orow = out + ((size_t)(b*NT + t))*NV;
    const int* idr = ids + b*NT;
    for (int s = tid; s < t; s += 256)
        atomicAdd(&orow[idr[s]], sc[s]*scale);
}

// ---------------- launcher ----------------------------------------------------
extern "C" void kernel_launch(void* const* d_in, const int* in_sizes, int n_in,
                              void* d_out, int out_size)
{
    const int*   ids     = (const int*)  d_in[0];
    const float* table   = (const float*)d_in[1];
    const float* w_ih    = (const float*)d_in[2];
    const float* w_hh    = (const float*)d_in[3];
    const float* b_ih    = (const float*)d_in[4];
    const float* b_hh    = (const float*)d_in[5];
    const float* wq      = (const float*)d_in[6];
    const float* bq      = (const float*)d_in[7];
    const float* wk      = (const float*)d_in[8];
    const float* bk      = (const float*)d_in[9];
    const float* wg      = (const float*)d_in[10];
    const float* bg      = (const float*)d_in[11];
    const float* w_fc    = (const float*)d_in[12];
    const float* b_fc    = (const float*)d_in[13];
    const float* w_proj  = (const float*)d_in[14];
    const float* b_proj  = (const float*)d_in[15];
    const float* out_b   = (const float*)d_in[16];
    const float* mscale  = (const float*)d_in[17];
    const float* smear_w = (const float*)d_in[18];
    const float* smear_l = (const float*)d_in[19];
    float* out = (float*)d_out;
    (void)in_sizes; (void)n_in; (void)out_size;

    void *p_emb, *p_xproj, *p_states, *p_head, *p_bfeat, *p_q, *p_k;
    void *p_e3, *p_wih3, *p_s3, *p_wfc3, *p_hd3, *p_wp3, *p_f3, *p_t3, *p_wq3, *p_wk3;
    cudaGetSymbolAddress(&p_emb,    g_emb);
    cudaGetSymbolAddress(&p_xproj,  g_xproj);
    cudaGetSymbolAddress(&p_states, g_states);
    cudaGetSymbolAddress(&p_head,   g_head);
    cudaGetSymbolAddress(&p_bfeat,  g_bfeat);
    cudaGetSymbolAddress(&p_q,      g_q);
    cudaGetSymbolAddress(&p_k,      g_k);
    cudaGetSymbolAddress(&p_e3,     x_e3);
    cudaGetSymbolAddress(&p_wih3,   x_wih3);
    cudaGetSymbolAddress(&p_s3,     x_s3);
    cudaGetSymbolAddress(&p_wfc3,   x_wfc3);
    cudaGetSymbolAddress(&p_hd3,    x_hd3);
    cudaGetSymbolAddress(&p_wp3,    x_wp3);
    cudaGetSymbolAddress(&p_f3,     x_f3);
    cudaGetSymbolAddress(&p_t3,     x_t3);
    cudaGetSymbolAddress(&p_wq3,    x_wq3);
    cudaGetSymbolAddress(&p_wk3,    x_wk3);

    const int gru_smem = (24*NH + 2*NH + 48 + 48) * (int)sizeof(float);
    cudaFuncSetAttribute(gru_kernel, cudaFuncAttributeMaxDynamicSharedMemorySize, gru_smem);

    #define EXPAND(srcp, dstp, nelem, mode) \
        expand3_kernel<<<((nelem)/8 + 255)/256, 256>>>((const float*)(srcp), (__nv_bfloat16*)(dstp), (nelem)/8, mode)

    // 1) embedding + smear (+ zero barrier counters and h0)
    embed_kernel<<<NROW, 256>>>(ids, table, smear_w, smear_l);
    // 2) x_proj = emb @ w_ih^T + b_ih        [4096,3072], K3=1536
    EXPAND(p_emb, p_e3,   NROW*NE,      0);
    EXPAND(w_ih,  p_wih3, 3*NH*NE,      1);
    hmma_gemm<<<dim3(24,32), 256>>>((const __nv_bfloat16*)p_e3, (const __nv_bfloat16*)p_wih3,
                                    b_ih, (float*)p_xproj, NROW, 3*NH, 3*NE, 0);
    // 3) GRU scan -> states
    gru_kernel<<<GRU_CTAS, 256, gru_smem>>>(w_hh, b_hh);
    // 4) head = relu^2(states @ w_fc^T + b_fc)  [4096,2048], K3=3072
    EXPAND(p_states, p_s3,   NROW*NH,   0);
    EXPAND(w_fc,     p_wfc3, 4*NE*NH,   1);
    hmma_gemm<<<dim3(16,32), 256>>>((const __nv_bfloat16*)p_s3, (const __nv_bfloat16*)p_wfc3,
                                    b_fc, (float*)p_head, NROW, 4*NE, 3*NH, 1);
    // 5) base_feat = head @ w_proj^T + b_proj   [4096,512], K3=6144
    EXPAND(p_head, p_hd3, NROW*4*NE,    0);
    EXPAND(w_proj, p_wp3, NE*4*NE,      1);
    hmma_gemm<<<dim3(4,32), 256>>>((const __nv_bfloat16*)p_hd3, (const __nv_bfloat16*)p_wp3,
                                   b_proj, (float*)p_bfeat, NROW, NE, 3*4*NE, 0);
    // 6) logits = base_feat @ emb_table^T + out_b -> d_out [4096,32000], K3=1536
    EXPAND(p_bfeat, p_f3, NROW*NE,      0);
    EXPAND(table,   p_t3, NV*NE,        1);
    hmma_gemm<<<dim3(250,32), 256>>>((const __nv_bfloat16*)p_f3, (const __nv_bfloat16*)p_t3,
                                     out_b, out, NROW, NV, 3*NE, 0);
    // 7) q, k via HMMA (reuse x_s3)              [4096,128], K3=3072
    EXPAND(wq, p_wq3, NM*NH, 1);
    EXPAND(wk, p_wk3, NM*NH, 1);
    hmma_gemm<<<dim3(1,32), 256>>>((const __nv_bfloat16*)p_s3, (const __nv_bfloat16*)p_wq3,
                                   bq, (float*)p_q, NROW, NM, 3*NH, 0);
    hmma_gemm<<<dim3(1,32), 256>>>((const __nv_bfloat16*)p_s3, (const __nv_bfloat16*)p_wk3,
                                   bk, (float*)p_k, NROW, NM, 3*NH, 0);
    // 8) g = sigmoid(states @ wg^T + bg)
    g_kernel<<<NROW/8, 256>>>(wg, bg);
    // 9) causal attention + scatter-add into d_out
    attn_kernel<<<dim3(NT, NB), 256>>>(ids, out, mscale);
    #undef EXPAND
}

// round 4
// speedup vs baseline: 1.4289x; 1.1129x over previous
#include <cuda_runtime.h>
#include <cuda_bf16.h>
#include <cstdint>

#define NB 2
#define NT 2048
#define NV 32000
#define NE 512
#define NH 1024
#define NM 128
#define NROW (NB*NT)      // 4096
#define GRU_CTAS 128

// ---------------- scratch (module-static device memory; no cudaMalloc) -------
__device__ __align__(16) float g_xproj[(size_t)NROW*3*NH];
__device__ __align__(16) float g_states[(size_t)NROW*NH];
__device__ __align__(16) float g_head[(size_t)NROW*4*NE];
__device__ __align__(16) float g_bfeat[NROW*NE];
__device__ __align__(16) float g_q[NROW*NM];
__device__ __align__(16) float g_k[NROW*NM];
__device__ __align__(16) float g_gate[NROW];
__device__ __align__(16) float g_h[2][NB*NH];
__device__ int g_cnt[NT];

// bf16 triple-expanded operands (K' = 3K)
__device__ __align__(16) __nv_bfloat16 x_e3  [(size_t)NROW*3*NE];
__device__ __align__(16) __nv_bfloat16 x_wih3[(size_t)3*NH*3*NE];
__device__ __align__(16) __nv_bfloat16 x_s3  [(size_t)NROW*3*NH];
__device__ __align__(16) __nv_bfloat16 x_wfc3[(size_t)4*NE*3*NH];
__device__ __align__(16) __nv_bfloat16 x_hd3 [(size_t)NROW*3*4*NE];
__device__ __align__(16) __nv_bfloat16 x_wp3 [(size_t)NE*3*4*NE];
__device__ __align__(16) __nv_bfloat16 x_f3  [(size_t)NROW*3*NE];
__device__ __align__(16) __nv_bfloat16 x_t3  [(size_t)NV*3*NE];
__device__ __align__(16) __nv_bfloat16 x_wq3 [(size_t)NM*3*NH];
__device__ __align__(16) __nv_bfloat16 x_wk3 [(size_t)NM*3*NH];

// ---------------- operand expansion: fp32 -> triple bf16 ---------------------
// A-mode (per element): [hi, hi, lo] ; B-mode: [hi, lo, hi]
__global__ void __launch_bounds__(256) expand3_kernel(
    const float* __restrict__ src, __nv_bfloat16* __restrict__ dst, int n8, int bmode)
{
    int i = blockIdx.x*256 + threadIdx.x;
    if (i >= n8) return;
    const float4* s4 = (const float4*)src + (size_t)i*2;
    float4 v0 = s4[0], v1 = s4[1];
    float a[8] = {v0.x, v0.y, v0.z, v0.w, v1.x, v1.y, v1.z, v1.w};
    __align__(16) __nv_bfloat16 o[24];
    #pragma unroll
    for (int j = 0; j < 8; j++) {
        float x = a[j];
        __nv_bfloat16 h = __float2bfloat16(x);
        __nv_bfloat16 l = __float2bfloat16(x - __bfloat162float(h));
        if (bmode) { o[3*j] = h; o[3*j+1] = l; o[3*j+2] = h; }
        else       { o[3*j] = h; o[3*j+1] = h; o[3*j+2] = l; }
    }
    uint4* d4 = (uint4*)(dst + (size_t)i*24);
    const uint4* ov = (const uint4*)o;
    d4[0] = ov[0]; d4[1] = ov[1]; d4[2] = ov[2];
}

// ================= HMMA (mma.sync) bf16 GEMM ================================
__device__ __forceinline__ uint32_t smem_u32(const void* p) {
    uint32_t a;
    asm("{ .reg .u64 t; cvta.to.shared.u64 t, %1; cvt.u32.u64 %0, t; }" : "=r"(a) : "l"(p));
    return a;
}

__device__ __forceinline__ int swoff(int row, int ch) {
    int p = row >> 1;
    return (p << 7) + (((((row & 1) << 2) | ch) ^ (p & 7)) << 4);
}

#define LDMX4(r0,r1,r2,r3, addr) \
    asm volatile("ldmatrix.sync.aligned.m8n8.x4.shared.b16 {%0,%1,%2,%3}, [%4];" \
        : "=r"(r0),"=r"(r1),"=r"(r2),"=r"(r3) : "r"(addr))

#define MMA16816(d, a, b0v, b1v) \
    asm volatile("mma.sync.aligned.m16n8k16.row.col.f32.bf16.bf16.f32 " \
        "{%0,%1,%2,%3}, {%4,%5,%6,%7}, {%8,%9}, {%0,%1,%2,%3};" \
        : "+f"((d)[0]),"+f"((d)[1]),"+f"((d)[2]),"+f"((d)[3]) \
        : "r"((a)[0]),"r"((a)[1]),"r"((a)[2]),"r"((a)[3]), "r"(b0v),"r"(b1v))

__global__ void __launch_bounds__(256) hmma_gemm(
    const __nv_bfloat16* __restrict__ A, const __nv_bfloat16* __restrict__ B,
    const float* __restrict__ bias, float* __restrict__ C,
    int M, int N, int K3, int act)
{
    __shared__ __align__(16) char smA[2][8192];
    __shared__ __align__(16) char smB[2][8192];

    const int tid  = threadIdx.x;
    const int lane = tid & 31, wid = tid >> 5;
    const int bm = blockIdx.y << 7, bn = blockIdx.x << 7;
    const int wm = (wid >> 2) << 6;
    const int wn = (wid & 3) << 5;

    const int row0 = tid >> 2,         ch0 = tid & 3;
    const int row1 = (tid + 256) >> 2, ch1 = tid & 3;
    const int so0 = swoff(row0, ch0), so1 = swoff(row1, ch1);
    const __nv_bfloat16* Ag0 = A + (size_t)(bm + row0)*K3 + ch0*8;
    const __nv_bfloat16* Ag1 = A + (size_t)(bm + row1)*K3 + ch1*8;
    const __nv_bfloat16* Bg0 = B + (size_t)(bn + row0)*K3 + ch0*8;
    const __nv_bfloat16* Bg1 = B + (size_t)(bn + row1)*K3 + ch1*8;

    const int g = lane >> 3, rr = lane & 7;
    const int lrow_a = wm + ((g & 1) << 3) + rr;
    const int lrow_b = wn + ((g & 1) << 3) + rr;
    const int kc = g >> 1;
    const uint32_t baseA0 = smem_u32(smA[0]), baseA1 = smem_u32(smA[1]);
    const uint32_t baseB0 = smem_u32(smB[0]), baseB1 = smem_u32(smB[1]);

    float acc[4][4][4];
    #pragma unroll
    for (int i = 0; i < 4; i++)
        #pragma unroll
        for (int j = 0; j < 4; j++)
            #pragma unroll
            for (int r = 0; r < 4; r++) acc[i][j][r] = 0.f;

    {
        uint4 a0 = *(const uint4*)Ag0, a1 = *(const uint4*)Ag1;
        uint4 b0 = *(const uint4*)Bg0, b1 = *(const uint4*)Bg1;
        *(uint4*)(smA[0] + so0) = a0; *(uint4*)(smA[0] + so1) = a1;
        *(uint4*)(smB[0] + so0) = b0; *(uint4*)(smB[0] + so1) = b1;
    }
    __syncthreads();

    const int nk = K3 >> 5;
    for (int kt = 0; kt < nk; kt++) {
        uint4 pa0, pa1, pb0, pb1;
        if (kt + 1 < nk) {
            const int ko = (kt + 1) << 5;
            pa0 = *(const uint4*)(Ag0 + ko); pa1 = *(const uint4*)(Ag1 + ko);
            pb0 = *(const uint4*)(Bg0 + ko); pb1 = *(const uint4*)(Bg1 + ko);
        }
        const uint32_t bA = (kt & 1) ? baseA1 : baseA0;
        const uint32_t bB = (kt & 1) ? baseB1 : baseB0;
        #pragma unroll
        for (int ks = 0; ks < 2; ks++) {
            const int chunk = (ks << 1) + kc;
            uint32_t af[4][4];
            #pragma unroll
            for (int mi = 0; mi < 4; mi++) {
                uint32_t ad = bA + swoff(lrow_a + (mi << 4), chunk);
                LDMX4(af[mi][0], af[mi][1], af[mi][2], af[mi][3], ad);
            }
            uint32_t bf[4][2];
            #pragma unroll
            for (int bi = 0; bi < 2; bi++) {
                uint32_t t0, t1, t2, t3;
                uint32_t ad = bB + swoff(lrow_b + (bi << 4), chunk);
                LDMX4(t0, t1, t2, t3, ad);
                bf[bi*2  ][0] = t0; bf[bi*2+1][0] = t1;
                bf[bi*2  ][1] = t2; bf[bi*2+1][1] = t3;
            }
            #pragma unroll
            for (int mi = 0; mi < 4; mi++)
                #pragma unroll
                for (int nj = 0; nj < 4; nj++)
                    MMA16816(acc[mi][nj], af[mi], bf[nj][0], bf[nj][1]);
        }
        if (kt + 1 < nk) {
            char* dA = (kt & 1) ? smA[0] : smA[1];
            char* dB = (kt & 1) ? smB[0] : smB[1];
            *(uint4*)(dA + so0) = pa0; *(uint4*)(dA + so1) = pa1;
            *(uint4*)(dB + so0) = pb0; *(uint4*)(dB + so1) = pb1;
            __syncthreads();
        }
    }

    const int q  = lane >> 2;
    const int c2 = (lane & 3) << 1;
    #pragma unroll
    for (int mi = 0; mi < 4; mi++) {
        #pragma unroll
        for (int nj = 0; nj < 4; nj++) {
            const int col  = bn + wn + (nj << 3) + c2;
            const int row  = bm + wm + (mi << 4) + q;
            float b0v = bias[col], b1v = bias[col+1];
            float v0 = acc[mi][nj][0] + b0v;
            float v1 = acc[mi][nj][1] + b1v;
            float v2 = acc[mi][nj][2] + b0v;
            float v3 = acc[mi][nj][3] + b1v;
            if (act == 1) {
                v0 = fmaxf(v0, 0.f); v0 *= v0;
                v1 = fmaxf(v1, 0.f); v1 *= v1;
                v2 = fmaxf(v2, 0.f); v2 *= v2;
                v3 = fmaxf(v3, 0.f); v3 *= v3;
            }
            *(float2*)&C[(size_t)row*N + col]       = make_float2(v0, v1);
            *(float2*)&C[(size_t)(row + 8)*N + col] = make_float2(v2, v3);
        }
    }
}

// ---------------- 1) embedding gather + smear -> x_e3 directly ---------------
__global__ void __launch_bounds__(256) embed_kernel(
    const int* __restrict__ ids, const float* __restrict__ table,
    const float* __restrict__ smear_w, const float* __restrict__ smear_lambda)
{
    const int bt  = blockIdx.x;
    const int tid = threadIdx.x;
    if (tid == 0 && bt < NT)    g_cnt[bt] = 0;
    if (tid == 1 && bt < NB*NH) g_h[0][bt] = 0.f;

    const int t  = bt % NT;
    const int id = ids[bt];
    __shared__ float sgate;

    float v = 0.f;
    if (tid < 24) v = table[(size_t)id*NE + tid] * smear_w[tid];
    if (tid < 32) {
        #pragma unroll
        for (int off = 16; off; off >>= 1) v += __shfl_xor_sync(0xffffffffu, v, off);
        if (tid == 0) {
            float lam = smear_lambda[0];
            sgate = (t > 0) ? lam * (1.f/(1.f + __expf(-v))) : 0.f;
        }
    }
    __syncthreads();
    const float gate = sgate;
    const int idp = (t > 0) ? ids[bt-1] : 0;
    const float* rc = table + (size_t)id *NE;
    const float* rp = table + (size_t)idp*NE;
    __nv_bfloat16* dst = x_e3 + (size_t)bt*3*NE;
    for (int e = tid; e < NE; e += 256) {
        float x = rc[e] + gate*rp[e];
        __nv_bfloat16 h = __float2bfloat16(x);
        __nv_bfloat16 l = __float2bfloat16(x - __bfloat162float(h));
        dst[3*e] = h; dst[3*e+1] = h; dst[3*e+2] = l;   // A-mode
    }
}

// ---------------- persistent GRU scan (register weights, acq/rel barrier) ----
// Warp w of CTA c owns j = c*8 + w: all 3 gates, both batches.
__global__ void __launch_bounds__(256) gru_kernel(
    const float* __restrict__ w_hh, const float* __restrict__ b_hh)
{
    __shared__ __align__(16) float sh[2*NH];
    const int tid  = threadIdx.x;
    const int lane = tid & 31, w = tid >> 5;
    const int j    = (blockIdx.x << 3) + w;

    // weights -> registers: wreg[gate][i] matches h chunk (i*32+lane) float4
    float4 wreg[3][8];
    #pragma unroll
    for (int g2 = 0; g2 < 3; g2++) {
        const float4* src = (const float4*)(w_hh + ((size_t)g2*NH + j)*NH);
        #pragma unroll
        for (int i = 0; i < 8; i++) wreg[g2][i] = src[i*32 + lane];
    }
    float bh_r = 0.f, bh_z = 0.f, bh_n = 0.f;
    if (lane < 2) { bh_r = b_hh[j]; bh_z = b_hh[NH + j]; bh_n = b_hh[2*NH + j]; }

    const float4* sh4 = (const float4*)sh;

    for (int t = 0; t < NT; t++) {
        // x prefetch: lane (gate*2+bb) for lane<6 (issued before barrier wait)
        float xv = 0.f;
        if (lane < 6) {
            const int g2 = lane >> 1, bb = lane & 1;
            xv = g_xproj[((size_t)(bb*NT + t))*(3*NH) + g2*NH + j];
        }
        if (t > 0) {
            if (tid == 0) {
                int v;
                do {
                    asm volatile("ld.acquire.gpu.global.s32 %0, [%1];"
                                 : "=r"(v) : "l"(g_cnt + (t-1)) : "memory");
                } while (v < GRU_CTAS);
            }
            __syncthreads();
        }
        {   // stage h (L2 -> SMEM)
            const float4* hs = (const float4*)g_h[t & 1];
            float4 a = __ldcg(hs + tid);
            float4 b = __ldcg(hs + 256 + tid);
            ((float4*)sh)[tid]       = a;
            ((float4*)sh)[256 + tid] = b;
        }
        __syncthreads();

        float ar0=0,ar1=0,az0=0,az1=0,an0=0,an1=0;
        #pragma unroll
        for (int i = 0; i < 8; i++) {
            float4 h0 = sh4[i*32 + lane];
            float4 h1 = sh4[256 + i*32 + lane];
            float4 w0 = wreg[0][i], w1 = wreg[1][i], w2 = wreg[2][i];
            ar0 += w0.x*h0.x + w0.y*h0.y + w0.z*h0.z + w0.w*h0.w;
            ar1 += w0.x*h1.x + w0.y*h1.y + w0.z*h1.z + w0.w*h1.w;
            az0 += w1.x*h0.x + w1.y*h0.y + w1.z*h0.z + w1.w*h0.w;
            az1 += w1.x*h1.x + w1.y*h1.y + w1.z*h1.z + w1.w*h1.w;
            an0 += w2.x*h0.x + w2.y*h0.y + w2.z*h0.z + w2.w*h0.w;
            an1 += w2.x*h1.x + w2.y*h1.y + w2.z*h1.z + w2.w*h1.w;
        }
        #pragma unroll
        for (int off = 16; off; off >>= 1) {
            ar0 += __shfl_xor_sync(0xffffffffu, ar0, off);
            ar1 += __shfl_xor_sync(0xffffffffu, ar1, off);
            az0 += __shfl_xor_sync(0xffffffffu, az0, off);
            az1 += __shfl_xor_sync(0xffffffffu, az1, off);
            an0 += __shfl_xor_sync(0xffffffffu, an0, off);
            an1 += __shfl_xor_sync(0xffffffffu, an1, off);
        }
        // distribute x values (held by lanes 0..5) to lanes 0,1
        const int bb = lane & 1;
        float xr = __shfl_sync(0xffffffffu, xv, 0 + bb);
        float xz = __shfl_sync(0xffffffffu, xv, 2 + bb);
        float xn = __shfl_sync(0xffffffffu, xv, 4 + bb);
        if (lane < 2) {
            float hr = (bb ? ar1 : ar0) + bh_r;
            float hz = (bb ? az1 : az0) + bh_z;
            float hn = (bb ? an1 : an0) + bh_n;
            float rr = 1.f/(1.f + __expf(-(xr + hr)));
            float zz = 1.f/(1.f + __expf(-(xz + hz)));
            float nn = tanhf(xn + rr*hn);
            float hold = sh[bb*NH + j];
            float hnew = (1.f - zz)*nn + zz*hold;
            g_states[((size_t)(bb*NT + t))*NH + j] = hnew;
            // triple-bf16 A-mode expansion written inline
            __nv_bfloat16 hh = __float2bfloat16(hnew);
            __nv_bfloat16 hl = __float2bfloat16(hnew - __bfloat162float(hh));
            __nv_bfloat16* s3 = x_s3 + ((size_t)(bb*NT + t))*(3*NH) + 3*j;
            s3[0] = hh; s3[1] = hh; s3[2] = hl;
            __stcg(&g_h[(t+1)&1][bb*NH + j], hnew);
        }
        __syncthreads();
        if (tid == 0) {
            asm volatile("red.release.gpu.global.add.s32 [%0], %1;"
                         :: "l"(g_cnt + t), "r"(1) : "memory");
        }
    }
}

// ---------------- g = sigmoid(states @ wg^T + bg) ----------------------------
__global__ void __launch_bounds__(256) g_kernel(
    const float* __restrict__ wg, const float* __restrict__ bg)
{
    const int row  = (blockIdx.x << 3) + (threadIdx.x >> 5);
    const int lane = threadIdx.x & 31;
    const float* s = g_states + (size_t)row*NH;
    float acc = 0.f;
    #pragma unroll 8
    for (int i = 0; i < 32; i++) acc += s[lane + (i<<5)] * wg[lane + (i<<5)];
    #pragma unroll
    for (int off = 16; off; off >>= 1) acc += __shfl_xor_sync(0xffffffffu, acc, off);
    if (lane == 0) g_gate[row] = 1.f/(1.f + __expf(-(acc + bg[0])));
}

// ---------------- causal attention + fused vocab scatter ---------------------
__global__ void __launch_bounds__(256) attn_kernel(
    const int* __restrict__ ids, float* __restrict__ out,
    const float* __restrict__ mscale_p)
{
    const int t = blockIdx.x;
    const int b = blockIdx.y;
    if (t == 0) return;

    __shared__ float sc[NT];
    __shared__ __align__(16) float qs[NM];
    __shared__ float red[8];
    const int tid = threadIdx.x;
    const int lane = tid & 31, wp = tid >> 5;

    if (tid < NM) qs[tid] = g_q[((size_t)(b*NT + t))*NM + tid];
    __syncthreads();
    const float4* q4 = (const float4*)qs;

    float lmax = -1e30f;
    for (int s = tid; s < t; s += 256) {
        const float4* k4 = (const float4*)(g_k + ((size_t)(b*NT + s))*NM);
        float acc = 0.f;
        #pragma unroll
        for (int c = 0; c < 32; c++) {
            float4 qv = q4[c]; float4 kv = k4[c];
            acc += qv.x*kv.x + qv.y*kv.y + qv.z*kv.z + qv.w*kv.w;
        }
        acc *= 0.0883883476483184f;
        sc[s] = acc;
        lmax = fmaxf(lmax, acc);
    }
    #pragma unroll
    for (int off = 16; off; off >>= 1) lmax = fmaxf(lmax, __shfl_xor_sync(0xffffffffu, lmax, off));
    if (lane == 0) red[wp] = lmax;
    __syncthreads();
    if (tid == 0) {
        float m = red[0];
        #pragma unroll
        for (int i = 1; i < 8; i++) m = fmaxf(m, red[i]);
        red[0] = m;
    }
    __syncthreads();
    const float smax = red[0];
    __syncthreads();

    float lsum = 0.f;
    for (int s = tid; s < t; s += 256) {
        float e = __expf(sc[s] - smax);
        sc[s] = e;
        lsum += e;
    }
    #pragma unroll
    for (int off = 16; off; off >>= 1) lsum += __shfl_xor_sync(0xffffffffu, lsum, off);
    if (lane == 0) red[wp] = lsum;
    __syncthreads();
    if (tid == 0) {
        float ssum = 0.f;
        #pragma unroll
        for (int i = 0; i < 8; i++) ssum += red[i];
        red[0] = ssum;
    }
    __syncthreads();
    const float ssum = fmaxf(red[0], 1e-6f);
    const float scale = g_gate[b*NT + t] * mscale_p[0] / ssum;

    float* orow = out + ((size_t)(b*NT + t))*NV;
    const int* idr = ids + b*NT;
    for (int s = tid; s < t; s += 256)
        atomicAdd(&orow[idr[s]], sc[s]*scale);
}

// ---------------- launcher ----------------------------------------------------
extern "C" void kernel_launch(void* const* d_in, const int* in_sizes, int n_in,
                              void* d_out, int out_size)
{
    const int*   ids     = (const int*)  d_in[0];
    const float* table   = (const float*)d_in[1];
    const float* w_ih    = (const float*)d_in[2];
    const float* w_hh    = (const float*)d_in[3];
    const float* b_ih    = (const float*)d_in[4];
    const float* b_hh    = (const float*)d_in[5];
    const float* wq      = (const float*)d_in[6];
    const float* bq      = (const float*)d_in[7];
    const float* wk      = (const float*)d_in[8];
    const float* bk      = (const float*)d_in[9];
    const float* wg      = (const float*)d_in[10];
    const float* bg      = (const float*)d_in[11];
    const float* w_fc    = (const float*)d_in[12];
    const float* b_fc    = (const float*)d_in[13];
    const float* w_proj  = (const float*)d_in[14];
    const float* b_proj  = (const float*)d_in[15];
    const float* out_b   = (const float*)d_in[16];
    const float* mscale  = (const float*)d_in[17];
    const float* smear_w = (const float*)d_in[18];
    const float* smear_l = (const float*)d_in[19];
    float* out = (float*)d_out;
    (void)in_sizes; (void)n_in; (void)out_size;

    void *p_xproj, *p_states, *p_head, *p_bfeat, *p_q, *p_k;
    void *p_e3, *p_wih3, *p_s3, *p_wfc3, *p_hd3, *p_wp3, *p_f3, *p_t3, *p_wq3, *p_wk3;
    cudaGetSymbolAddress(&p_xproj,  g_xproj);
    cudaGetSymbolAddress(&p_states, g_states);
    cudaGetSymbolAddress(&p_head,   g_head);
    cudaGetSymbolAddress(&p_bfeat,  g_bfeat);
    cudaGetSymbolAddress(&p_q,      g_q);
    cudaGetSymbolAddress(&p_k,      g_k);
    cudaGetSymbolAddress(&p_e3,     x_e3);
    cudaGetSymbolAddress(&p_wih3,   x_wih3);
    cudaGetSymbolAddress(&p_s3,     x_s3);
    cudaGetSymbolAddress(&p_wfc3,   x_wfc3);
    cudaGetSymbolAddress(&p_hd3,    x_hd3);
    cudaGetSymbolAddress(&p_wp3,    x_wp3);
    cudaGetSymbolAddress(&p_f3,     x_f3);
    cudaGetSymbolAddress(&p_t3,     x_t3);
    cudaGetSymbolAddress(&p_wq3,    x_wq3);
    cudaGetSymbolAddress(&p_wk3,    x_wk3);

    #define EXPAND(srcp, dstp, nelem, mode) \
        expand3_kernel<<<((nelem)/8 + 255)/256, 256>>>((const float*)(srcp), (__nv_bfloat16*)(dstp), (nelem)/8, mode)

    // 1) embedding + smear -> x_e3 (+ zero barrier counters and h0)
    embed_kernel<<<NROW, 256>>>(ids, table, smear_w, smear_l);
    // 2) x_proj = emb @ w_ih^T + b_ih        [4096,3072], K3=1536
    EXPAND(w_ih,  p_wih3, 3*NH*NE,      1);
    hmma_gemm<<<dim3(24,32), 256>>>((const __nv_bfloat16*)p_e3, (const __nv_bfloat16*)p_wih3,
                                    b_ih, (float*)p_xproj, NROW, 3*NH, 3*NE, 0);
    // 3) GRU scan -> g_states + x_s3
    gru_kernel<<<GRU_CTAS, 256>>>(w_hh, b_hh);
    // 4) head = relu^2(states @ w_fc^T + b_fc)  [4096,2048], K3=3072
    EXPAND(w_fc,     p_wfc3, 4*NE*NH,   1);
    hmma_gemm<<<dim3(16,32), 256>>>((const __nv_bfloat16*)p_s3, (const __nv_bfloat16*)p_wfc3,
                                    b_fc, (float*)p_head, NROW, 4*NE, 3*NH, 1);
    // 5) base_feat = head @ w_proj^T + b_proj   [4096,512], K3=6144
    EXPAND(p_head, p_hd3, NROW*4*NE,    0);
    EXPAND(w_proj, p_wp3, NE*4*NE,      1);
    hmma_gemm<<<dim3(4,32), 256>>>((const __nv_bfloat16*)p_hd3, (const __nv_bfloat16*)p_wp3,
                                   b_proj, (float*)p_bfeat, NROW, NE, 3*4*NE, 0);
    // 6) logits = base_feat @ emb_table^T + out_b -> d_out [4096,32000], K3=1536
    EXPAND(p_bfeat, p_f3, NROW*NE,      0);
    EXPAND(table,   p_t3, NV*NE,        1);
    hmma_gemm<<<dim3(250,32), 256>>>((const __nv_bfloat16*)p_f3, (const __nv_bfloat16*)p_t3,
                                     out_b, out, NROW, NV, 3*NE, 0);
    // 7) q, k via HMMA (reuse x_s3)              [4096,128], K3=3072
    EXPAND(wq, p_wq3, NM*NH, 1);
    EXPAND(wk, p_wk3, NM*NH, 1);
    hmma_gemm<<<dim3(1,32), 256>>>((const __nv_bfloat16*)p_s3, (const __nv_bfloat16*)p_wq3,
                                   bq, (float*)p_q, NROW, NM, 3*NH, 0);
    hmma_gemm<<<dim3(1,32), 256>>>((const __nv_bfloat16*)p_s3, (const __nv_bfloat16*)p_wk3,
                                   bk, (float*)p_k, NROW, NM, 3*NH, 0);
    // 8) g = sigmoid(states @ wg^T + bg)
    g_kernel<<<NROW/8, 256>>>(wg, bg);
    // 9) causal attention + scatter-add into d_out
    attn_kernel<<<dim3(NT, NB), 256>>>(ids, out, mscale);
    #undef EXPAND
}